// round 5
// baseline (speedup 1.0000x reference)
#include <cuda_runtime.h>
#include <stdint.h>

// HierarchicalRingTopK: 3x3x3 VALID conv (120 ch) + 4-level gated top-k keep.
// x: (8,3,256,256) f32, w: (120,3,3,3) f32, b: (120,) f32
// out: (8,120,254,254) f32
//
// Thread = one output pixel. Per level: conv -> exact-order key encode ->
// k max-extractions from a per-thread shared-memory column -> gate mask for
// next level. Keys are rotl(float_bits,1): bits>>? magnitude in high 31 bits,
// sign in LSB; exactly invertible so written values are full fp32 precision.
//
// Conv accumulation replicates XLA:CPU's Eigen path: serial fp32 FMA chain
// over the 27 taps in NHWC patch order (kh slowest, kw, c fastest), starting
// from 0, bias added afterwards as a separately-rounded fp32 add. Matching
// the reference's rounding sequence eliminates top-k boundary flips.
//
// Top-k semantics match jax.lax.top_k(|x|): magnitude compare, ties broken
// by LOWER index (strict > scan). descending_mask excludes exact zeros.

#define BT 128
#define OH 254
#define OW 254
#define PLANE (OH * OW)          // 64516
#define NPIX (8 * PLANE)         // 516128
#define NCH 120

__global__ void __launch_bounds__(BT)
hrtk_kernel(const float* __restrict__ x,
            const float* __restrict__ w,
            const float* __restrict__ b,
            float* __restrict__ out)
{
    __shared__ float    wsh[NCH * 28];      // 27 weights + bias per channel
    __shared__ unsigned sEnc[64 * BT];      // per-thread key column (max level n=64)

    const int t = threadIdx.x;

    // Stage weights+bias: wsh[c*28 + q] = q<27 ? w[c*27+q] : b[c]
    for (int q = t; q < NCH * 28; q += BT) {
        int c = q / 28;
        int r = q - c * 28;
        wsh[q] = (r < 27) ? w[c * 27 + r] : b[c];
    }
    __syncthreads();

    const int p = blockIdx.x * BT + t;
    if (p >= NPIX) return;

    const int ww = p % OW;
    const int rest = p / OW;
    const int hh = rest % OH;
    const int bb = rest / OH;

    // Load 3x3x3 input window into registers (heavy L1/L2 reuse across threads)
    float win[27];
    const float* xb = x + (size_t)bb * (3 * 65536) + hh * 256 + ww;
#pragma unroll
    for (int ci = 0; ci < 3; ci++)
#pragma unroll
        for (int kh = 0; kh < 3; kh++)
#pragma unroll
            for (int kw = 0; kw < 3; kw++)
                win[ci * 9 + kh * 3 + kw] = __ldg(xb + ci * 65536 + kh * 256 + kw);

    float* ob = out + (size_t)bb * (NCH * PLANE) + hh * OW + ww;  // + c*PLANE per channel

    unsigned long long gate = ~0ull;   // level 0: everything enabled
    int base = 0;

#pragma unroll
    for (int lvl = 0; lvl < 4; lvl++) {
        const int n = 8 << lvl;   // 8,16,32,64
        const int k = 2 << lvl;   // 2,4,8,16

        // ---- conv + encode + zero-prefill ----
#pragma unroll 2
        for (int i = 0; i < n; i++) {
            const int c = base + i;
            const float4* wv = (const float4*)(wsh + c * 28);
            float wr[28];
            *(float4*)&wr[0]  = wv[0];
            *(float4*)&wr[4]  = wv[1];
            *(float4*)&wr[8]  = wv[2];
            *(float4*)&wr[12] = wv[3];
            *(float4*)&wr[16] = wv[4];
            *(float4*)&wr[20] = wv[5];
            *(float4*)&wr[24] = wv[6];

            // Serial FMA chain in NHWC patch order (kh, kw, c — c innermost),
            // bias added afterwards: replicates XLA:CPU/Eigen rounding.
            float acc = 0.0f;
#pragma unroll
            for (int kh = 0; kh < 3; kh++)
#pragma unroll
                for (int kw = 0; kw < 3; kw++)
#pragma unroll
                    for (int ci = 0; ci < 3; ci++) {
                        const int q = ci * 9 + kh * 3 + kw;
                        acc = fmaf(win[q], wr[q], acc);
                    }
            const float act = acc + wr[27];

            const unsigned bits = __float_as_uint(act);
            unsigned key = __funnelshift_l(bits, bits, 1);   // mag in [31:1], sign LSB
            const unsigned live = (unsigned)(gate >> i) & 1u;
            key = live ? key : 0u;
            sEnc[i * BT + t] = key;
            ob[c * PLANE] = 0.0f;   // prefill; overwritten below if selected
        }

        // ---- k exact max-extractions (magnitude compare, lower index wins) ----
        unsigned selmask = 0u;
        for (int s = 0; s < k; s++) {
            unsigned mmag = 0u, mfull = 0u;
            int mi = -1;
#pragma unroll 4
            for (int i = 0; i < n; i++) {
                const unsigned u = sEnc[i * BT + t];
                const unsigned um = u >> 1;          // |v| only
                if (um > mmag) { mmag = um; mfull = u; mi = i; }
            }
            if (mi >= 0) {                           // nonzero magnitude found
                ob[(base + mi) * PLANE] =
                    __uint_as_float(__funnelshift_r(mfull, mfull, 1)); // exact decode
                sEnc[mi * BT + t] = 0u;
                selmask |= (1u << mi);               // nonzero => mask bit (selected != 0)
            }
        }

        // ---- gating mask for next level (targets 2j..2j+3 mod 2n) ----
        if (lvl < 3) {
            unsigned long long gg = 0ull;
            unsigned sm2 = selmask;
            while (sm2) {
                const int j = __ffs(sm2) - 1;
                sm2 &= sm2 - 1;
                gg |= 0xFull << (2 * j);
                if (2 * j + 3 > 63)                 // only j==31 (L2->L3 wrap)
                    gg |= 0xFull >> (64 - 2 * j);
            }
            const int Wn = n * 2;
            if (Wn < 64)
                gg = (gg | (gg >> Wn)) & ((1ull << Wn) - 1ull);
            gate = gg;
        }
        base += n;
    }
}

extern "C" void kernel_launch(void* const* d_in, const int* in_sizes, int n_in,
                              void* d_out, int out_size)
{
    const float* x = (const float*)d_in[0];
    const float* w = (const float*)d_in[1];
    const float* b = (const float*)d_in[2];
    float* out = (float*)d_out;

    const int grid = (NPIX + BT - 1) / BT;
    hrtk_kernel<<<grid, BT>>>(x, w, b, out);
}

// round 6
// speedup vs baseline: 1.6515x; 1.6515x over previous
#include <cuda_runtime.h>
#include <stdint.h>

// HierarchicalRingTopK: 3x3x3 VALID conv (120 ch) + 4-level gated top-k keep.
// x: (8,3,256,256) f32, w: (120,3,3,3) f32, b: (120,) f32 -> out: (8,120,254,254) f32
//
// FROZEN NUMERICS (R4 gave rel_err == 0.0): serial fp32 FMA chain over the 27
// taps in NHWC patch order (kh slowest, kw, c fastest) from 0, bias added as a
// separate fp32 add. Keys rotl(bits,1): magnitude in [31:1], sign LSB, exactly
// invertible. Top-k: magnitude strict-> scan, lower index wins ties.
//
// R5 perf changes:
//  - Two-level selection: per-group(8) max magnitudes in shared; extraction =
//    argmax over groups + single 8-slot rescan (leaf + 2nd max in one pass).
//    Cuts dominant scan work ~4x vs k full passes over n.
//  - Warp-uniform dead-group skip: union gate across warp via shuffles; groups
//    of 8 channels dead in all lanes skip conv entirely (zeros only).

#define BT 128
#define OH 254
#define OW 254
#define PLANE (OH * OW)          // 64516
#define NPIX (8 * PLANE)         // 516128
#define NCH 120

__global__ void __launch_bounds__(BT)
hrtk_kernel(const float* __restrict__ x,
            const float* __restrict__ w,
            const float* __restrict__ b,
            float* __restrict__ out)
{
    __shared__ float    wsh[NCH * 28];      // 27 weights + bias per channel
    __shared__ unsigned sEnc[64 * BT];      // per-thread key columns (max n=64)
    __shared__ unsigned gmagS[8 * BT];      // per-thread group-max magnitudes

    const int t = threadIdx.x;

    for (int q = t; q < NCH * 28; q += BT) {
        int c = q / 28;
        int r = q - c * 28;
        wsh[q] = (r < 27) ? w[c * 27 + r] : b[c];
    }
    __syncthreads();

    const int p = blockIdx.x * BT + t;
    if (p >= NPIX) return;
    // NPIX % BT == 32: the tail block keeps exactly one FULL warp alive, so
    // full-mask warp shuffles below are safe in every surviving warp.

    const int ww = p % OW;
    const int rest = p / OW;
    const int hh = rest % OH;
    const int bb = rest / OH;

    float win[27];
    const float* xb = x + (size_t)bb * (3 * 65536) + hh * 256 + ww;
#pragma unroll
    for (int ci = 0; ci < 3; ci++)
#pragma unroll
        for (int kh = 0; kh < 3; kh++)
#pragma unroll
            for (int kw = 0; kw < 3; kw++)
                win[ci * 9 + kh * 3 + kw] = __ldg(xb + ci * 65536 + kh * 256 + kw);

    float* ob = out + (size_t)bb * (NCH * PLANE) + hh * OW + ww;

    unsigned long long gate = ~0ull;
    int base = 0;

#pragma unroll
    for (int lvl = 0; lvl < 4; lvl++) {
        const int n = 8 << lvl;   // 8,16,32,64
        const int k = 2 << lvl;   // 2,4,8,16
        const int G = n >> 3;     // groups of 8

        // Union of gates across the warp (warp-uniform liveness).
        unsigned long long ugate = ~0ull;
        if (lvl > 0) {
            unsigned lo = (unsigned)gate, hi = (unsigned)(gate >> 32);
#pragma unroll
            for (int o = 16; o; o >>= 1) {
                lo |= __shfl_xor_sync(0xffffffffu, lo, o);
                hi |= __shfl_xor_sync(0xffffffffu, hi, o);
            }
            ugate = ((unsigned long long)hi << 32) | lo;
        }

        // ---- conv + encode + zero-prefill + group-max build ----
#pragma unroll 1
        for (int g = 0; g < G; g++) {
            const int ib = g << 3;
            unsigned gm = 0u;
            if (((ugate >> ib) & 0xFFull) == 0ull) {
                // whole group dead in every lane of the warp: zeros only
#pragma unroll
                for (int j = 0; j < 8; j++) {
                    sEnc[(ib + j) * BT + t] = 0u;
                    ob[(base + ib + j) * PLANE] = 0.0f;
                }
            } else {
#pragma unroll
                for (int j = 0; j < 8; j++) {
                    const int i = ib + j;
                    const int c = base + i;
                    const float4* wv = (const float4*)(wsh + c * 28);
                    float wr[28];
                    *(float4*)&wr[0]  = wv[0];
                    *(float4*)&wr[4]  = wv[1];
                    *(float4*)&wr[8]  = wv[2];
                    *(float4*)&wr[12] = wv[3];
                    *(float4*)&wr[16] = wv[4];
                    *(float4*)&wr[20] = wv[5];
                    *(float4*)&wr[24] = wv[6];

                    // FROZEN: Eigen/NHWC order (kh, kw, c innermost), bias after.
                    float acc = 0.0f;
#pragma unroll
                    for (int kh = 0; kh < 3; kh++)
#pragma unroll
                        for (int kw = 0; kw < 3; kw++)
#pragma unroll
                            for (int ci = 0; ci < 3; ci++) {
                                const int q = ci * 9 + kh * 3 + kw;
                                acc = fmaf(win[q], wr[q], acc);
                            }
                    const float act = acc + wr[27];

                    const unsigned bits = __float_as_uint(act);
                    unsigned key = __funnelshift_l(bits, bits, 1);
                    const unsigned live = (unsigned)(gate >> i) & 1u;
                    key = live ? key : 0u;
                    sEnc[i * BT + t] = key;
                    ob[c * PLANE] = 0.0f;
                    const unsigned um = key >> 1;
                    if (um > gm) gm = um;   // ascending j: first-wins preserved
                }
            }
            gmagS[g * BT + t] = gm;
        }

        // ---- k extractions via group maxes ----
        unsigned long long selmask = 0ull;
#pragma unroll 1
        for (int s = 0; s < k; s++) {
            unsigned bm = 0u;
            int bg = 0;
#pragma unroll
            for (int g = 0; g < 8; g++) {
                if (g < G) {
                    const unsigned u = gmagS[g * BT + t];
                    if (u > bm) { bm = u; bg = g; }   // strict >: lowest group wins
                }
            }
            if (bm) {
                // rescan winning group: first j with mag==bm is the global
                // argmax (lower index wins); simultaneously find 2nd max.
                unsigned m2 = 0u, ufull = 0u, found = 0u;
                int leaf = 0;
                const int gb = bg << 3;
#pragma unroll
                for (int j = 0; j < 8; j++) {
                    const unsigned u = sEnc[(gb + j) * BT + t];
                    const unsigned um = u >> 1;
                    if (um == bm && !found) { found = 1u; leaf = j; ufull = u; }
                    else if (um > m2) m2 = um;
                }
                const int mi = gb + leaf;
                ob[(base + mi) * PLANE] =
                    __uint_as_float(__funnelshift_r(ufull, ufull, 1));
                sEnc[mi * BT + t] = 0u;
                gmagS[bg * BT + t] = m2;
                selmask |= 1ull << mi;
            }
        }

        // ---- gating mask for next level (targets 2j..2j+3 mod 2n) ----
        if (lvl < 3) {
            unsigned long long gg = 0ull;
            unsigned sm2 = (unsigned)selmask;   // n<=32 at lvl<3
            while (sm2) {
                const int j = __ffs(sm2) - 1;
                sm2 &= sm2 - 1;
                gg |= 0xFull << (2 * j);
                if (2 * j + 3 > 63)
                    gg |= 0xFull >> (64 - 2 * j);
            }
            const int Wn = n * 2;
            if (Wn < 64)
                gg = (gg | (gg >> Wn)) & ((1ull << Wn) - 1ull);
            gate = gg;
        }
        base += n;
    }
}

extern "C" void kernel_launch(void* const* d_in, const int* in_sizes, int n_in,
                              void* d_out, int out_size)
{
    const float* x = (const float*)d_in[0];
    const float* w = (const float*)d_in[1];
    const float* b = (const float*)d_in[2];
    float* out = (float*)d_out;

    const int grid = (NPIX + BT - 1) / BT;
    hrtk_kernel<<<grid, BT>>>(x, w, b, out);
}

// round 7
// speedup vs baseline: 1.7818x; 1.0789x over previous
#include <cuda_runtime.h>
#include <stdint.h>

// HierarchicalRingTopK: 3x3x3 VALID conv (120 ch) + 4-level gated top-k keep.
// x: (8,3,256,256) f32, w: (120,3,3,3) f32, b: (120,) f32 -> out: (8,120,254,254) f32
//
// FROZEN NUMERICS (R4/R5 gave rel_err == 0.0): per-channel serial fp32 FMA
// chain over the 27 taps in NHWC patch order (kh slowest, kw, c fastest) from
// 0, bias added as a separate fp32 add. Keys rotl(bits,1). Top-k: magnitude
// strict-> scan, lower index wins ties.
//
// R6 perf changes:
//  - f32x2 packed conv: two adjacent channels share one fma.rn.f32x2 chain.
//    Each 64-bit lane is an independent fp32 rn-FMA -> bit-identical numerics,
//    half the FMA instruction issue.
//  - Group-max values kept in registers (unrolled cmp/sel) instead of shared:
//    removes ~300 L1 wavefronts/thread from the hottest pipe.

#define BT 128
#define OH 254
#define OW 254
#define PLANE (OH * OW)          // 64516
#define NPIX (8 * PLANE)         // 516128
#define NCH 120
#define NPAIR (NCH / 2)          // 60 channel pairs

__device__ __forceinline__ unsigned long long ffma2(unsigned long long a,
                                                    unsigned long long bb_,
                                                    unsigned long long c) {
    unsigned long long d;
    asm("fma.rn.f32x2 %0, %1, %2, %3;" : "=l"(d) : "l"(a), "l"(bb_), "l"(c));
    return d;
}
__device__ __forceinline__ unsigned long long pack2(float lo, float hi) {
    unsigned long long r;
    asm("mov.b64 %0, {%1, %2};" : "=l"(r) : "f"(lo), "f"(hi));
    return r;
}
__device__ __forceinline__ void unpack2(unsigned long long v, float& lo, float& hi) {
    asm("mov.b64 {%0, %1}, %2;" : "=f"(lo), "=f"(hi) : "l"(v));
}

__global__ void __launch_bounds__(BT, 4)
hrtk_kernel(const float* __restrict__ x,
            const float* __restrict__ w,
            const float* __restrict__ b,
            float* __restrict__ out)
{
    // Pair-interleaved weights: wsh2[pr*56 + 2q+e] = w[2pr+e][q], e in {0,1};
    // wsh2[pr*56 + 54+e] = b[2pr+e].
    __shared__ float    wsh2[NPAIR * 56];   // 13440 B
    __shared__ unsigned sEnc[64 * BT];      // 32768 B  (per-thread key columns)

    const int t = threadIdx.x;

    for (int q = t; q < NPAIR * 56; q += BT) {
        const int pr = q / 56;
        const int r  = q - pr * 56;
        float v;
        if (r < 54) v = w[(pr * 2 + (r & 1)) * 27 + (r >> 1)];
        else        v = b[pr * 2 + (r - 54)];
        wsh2[q] = v;
    }
    __syncthreads();

    const int p = blockIdx.x * BT + t;
    if (p >= NPIX) return;
    // NPIX % BT == 32: tail block keeps exactly one FULL warp alive, so
    // full-mask shuffles below are safe in every surviving warp.

    const int ww = p % OW;
    const int rest = p / OW;
    const int hh = rest % OH;
    const int bb = rest / OH;

    // 3x3x3 window, duplicated into f32x2 lanes once.
    unsigned long long win2[27];
    const float* xb = x + (size_t)bb * (3 * 65536) + hh * 256 + ww;
#pragma unroll
    for (int ci = 0; ci < 3; ci++)
#pragma unroll
        for (int kh = 0; kh < 3; kh++)
#pragma unroll
            for (int kw = 0; kw < 3; kw++) {
                const float v = __ldg(xb + ci * 65536 + kh * 256 + kw);
                win2[ci * 9 + kh * 3 + kw] = pack2(v, v);
            }

    float* ob = out + (size_t)bb * (NCH * PLANE) + hh * OW + ww;

    unsigned long long gate = ~0ull;
    int base = 0;

#pragma unroll
    for (int lvl = 0; lvl < 4; lvl++) {
        const int n = 8 << lvl;   // 8,16,32,64
        const int k = 2 << lvl;   // 2,4,8,16
        const int G = n >> 3;     // groups of 8 channels

        // Warp-union of gates (uniform liveness for dead-group skip).
        unsigned long long ugate = ~0ull;
        if (lvl > 0) {
            unsigned lo = (unsigned)gate, hi = (unsigned)(gate >> 32);
#pragma unroll
            for (int o = 16; o; o >>= 1) {
                lo |= __shfl_xor_sync(0xffffffffu, lo, o);
                hi |= __shfl_xor_sync(0xffffffffu, hi, o);
            }
            ugate = ((unsigned long long)hi << 32) | lo;
        }

        unsigned gmag[8];
#pragma unroll
        for (int g = 0; g < 8; g++) gmag[g] = 0u;

        // ---- conv + encode + zero-prefill + group-max build ----
#pragma unroll
        for (int g = 0; g < G; g++) {
            const int ib = g << 3;
            unsigned gm = 0u;
            if (((ugate >> ib) & 0xFFull) == 0ull) {
#pragma unroll
                for (int j = 0; j < 8; j++) {
                    sEnc[(ib + j) * BT + t] = 0u;
                    ob[(base + ib + j) * PLANE] = 0.0f;
                }
            } else {
#pragma unroll
                for (int j2 = 0; j2 < 4; j2++) {            // 4 channel-pairs
                    const int i0 = ib + j2 * 2;
                    const int pr = (base + i0) >> 1;
                    const float4* wv = (const float4*)(wsh2 + pr * 56);
                    float wrp[56];
#pragma unroll
                    for (int z = 0; z < 14; z++) *(float4*)&wrp[4 * z] = wv[z];

                    // FROZEN: Eigen/NHWC tap order, per-lane serial fp32 chain.
                    unsigned long long acc = 0ull;
#pragma unroll
                    for (int kh = 0; kh < 3; kh++)
#pragma unroll
                        for (int kw = 0; kw < 3; kw++)
#pragma unroll
                            for (int ci = 0; ci < 3; ci++) {
                                const int q = ci * 9 + kh * 3 + kw;
                                acc = ffma2(win2[q],
                                            *(const unsigned long long*)&wrp[2 * q],
                                            acc);
                            }
                    float a0, a1;
                    unpack2(acc, a0, a1);
                    const float act0 = a0 + wrp[54];
                    const float act1 = a1 + wrp[55];

                    const unsigned b0 = __float_as_uint(act0);
                    const unsigned b1 = __float_as_uint(act1);
                    unsigned k0 = __funnelshift_l(b0, b0, 1);
                    unsigned k1 = __funnelshift_l(b1, b1, 1);
                    k0 = ((unsigned)(gate >> (i0    )) & 1u) ? k0 : 0u;
                    k1 = ((unsigned)(gate >> (i0 + 1)) & 1u) ? k1 : 0u;
                    sEnc[(i0    ) * BT + t] = k0;
                    sEnc[(i0 + 1) * BT + t] = k1;
                    ob[(base + i0    ) * PLANE] = 0.0f;
                    ob[(base + i0 + 1) * PLANE] = 0.0f;
                    const unsigned um0 = k0 >> 1, um1 = k1 >> 1;
                    if (um0 > gm) gm = um0;                  // ascending order:
                    if (um1 > gm) gm = um1;                  // first-wins kept
                }
            }
            gmag[g] = gm;
        }

        // ---- k extractions: register group-max scan + one 8-slot rescan ----
        unsigned long long selmask = 0ull;
#pragma unroll 1
        for (int s = 0; s < k; s++) {
            unsigned bm = 0u;
            int bg = 0;
#pragma unroll
            for (int g = 0; g < 8; g++)
                if (g < G && gmag[g] > bm) { bm = gmag[g]; bg = g; }  // strict >
            if (!bm) break;                       // all remaining keys are zero

            unsigned m2 = 0u, ufull = 0u, found = 0u;
            int leaf = 0;
            const int gb = bg << 3;
#pragma unroll
            for (int j = 0; j < 8; j++) {
                const unsigned u = sEnc[(gb + j) * BT + t];
                const unsigned um = u >> 1;
                if (um == bm && !found) { found = 1u; leaf = j; ufull = u; }
                else if (um > m2) m2 = um;
            }
            const int mi = gb + leaf;
            ob[(base + mi) * PLANE] =
                __uint_as_float(__funnelshift_r(ufull, ufull, 1));
            sEnc[mi * BT + t] = 0u;
#pragma unroll
            for (int g = 0; g < 8; g++)
                if (g == bg) gmag[g] = m2;
            selmask |= 1ull << mi;
        }

        // ---- gating mask for next level (targets 2j..2j+3 mod 2n) ----
        if (lvl < 3) {
            unsigned long long gg = 0ull;
            unsigned sm2 = (unsigned)selmask;     // n<=32 at lvl<3
            while (sm2) {
                const int j = __ffs(sm2) - 1;
                sm2 &= sm2 - 1;
                gg |= 0xFull << (2 * j);
                if (2 * j + 3 > 63)               // only j==31 (L2->L3 wrap)
                    gg |= 0xFull >> (64 - 2 * j);
            }
            const int Wn = n * 2;
            if (Wn < 64)
                gg = (gg | (gg >> Wn)) & ((1ull << Wn) - 1ull);
            gate = gg;
        }
        base += n;
    }
}

extern "C" void kernel_launch(void* const* d_in, const int* in_sizes, int n_in,
                              void* d_out, int out_size)
{
    const float* x = (const float*)d_in[0];
    const float* w = (const float*)d_in[1];
    const float* b = (const float*)d_in[2];
    float* out = (float*)d_out;

    const int grid = (NPIX + BT - 1) / BT;
    hrtk_kernel<<<grid, BT>>>(x, w, b, out);
}